// round 1
// baseline (speedup 1.0000x reference)
#include <cuda_runtime.h>
#include <cstdint>
#include <cstddef>

// ---------------- problem constants ----------------
#define BB    8
#define CIN   3
#define IMG   128
#define PATCH 4
#define DIMC  192          // DIM
#define DEPTH 2
#define DIN   384          // 2*DIM
#define NS    16           // N (state)
#define RR    12           // R
#define KDIR  4            // K directions
#define HP    32
#define LTOK  1024         // L = HP*HP
#define NTOK  (BB*LTOK)    // 8192 tokens

// ---------------- scratch (no cudaMalloc allowed) ----------------
__device__ float g_y  [(size_t)NTOK*DIMC];        // residual stream [t][c]
__device__ float g_lny[(size_t)NTOK*DIMC];        // LN'd stream     [t][c]
__device__ float g_xz [(size_t)NTOK*2*DIN];       // in_proj out     [t][768]
__device__ float g_xc [(size_t)NTOK*DIN];         // conv+silu out   [t][d]  (t = b*1024 + h*32+w)
__device__ float g_dt [(size_t)BB*KDIR*LTOK*DIN]; // softplus dt     [b][k][l][d]
__device__ float g_BC [(size_t)BB*KDIR*LTOK*32];  // Bs(16)+Cs(16)   [b][k][l][32]
__device__ float g_ys [(size_t)BB*KDIR*LTOK*DIN]; // scan out        [b][k][l][d]
__device__ float g_yo [(size_t)NTOK*DIN];         // gated LN out    [t][d]

// ---------------- fast exp (FMA pipe, no MUFU) ----------------
// exp(x) = 2^(x*log2e); i = rint(z); f = z-i; 2^f via deg-6 Taylor of exp(f*ln2).
// rel err ~1e-7 for |f|<=0.5. Clamped to [-80, 80].
__device__ __forceinline__ float fast_exp(float x) {
    x = fminf(fmaxf(x, -80.f), 80.f);
    float z = x * 1.4426950408889634f;
    float r = rintf(z);
    float f = z - r;
    int   i = (int)r;
    float p =          1.5403530e-4f;
    p = fmaf(p, f, 1.3333558e-3f);
    p = fmaf(p, f, 9.6181291e-3f);
    p = fmaf(p, f, 5.5504109e-2f);
    p = fmaf(p, f, 2.4022651e-1f);
    p = fmaf(p, f, 6.9314718e-1f);
    p = fmaf(p, f, 1.0f);
    return p * __int_as_float((i + 127) << 23);
}

__device__ __forceinline__ float silu_f(float v) {
    return v / (1.f + fast_exp(-v));
}

// ---------------- block LayerNorm reduce (nth multiple of 32, <=512) ----------------
__device__ __forceinline__ float2 block_meanvar(float v, int tid, int nth, float* red) {
    float s = v, q = v * v;
    #pragma unroll
    for (int o = 16; o; o >>= 1) {
        s += __shfl_xor_sync(0xffffffffu, s, o);
        q += __shfl_xor_sync(0xffffffffu, q, o);
    }
    if ((tid & 31) == 0) { red[tid >> 5] = s; red[16 + (tid >> 5)] = q; }
    __syncthreads();
    if (tid < 32) {
        int nw = nth >> 5;
        float a = (tid < nw) ? red[tid]      : 0.f;
        float c = (tid < nw) ? red[16 + tid] : 0.f;
        #pragma unroll
        for (int o = 8; o; o >>= 1) {
            a += __shfl_xor_sync(0xffffffffu, a, o);
            c += __shfl_xor_sync(0xffffffffu, c, o);
        }
        if (tid == 0) { red[32] = a; red[33] = c; }
    }
    __syncthreads();
    float inv_n = 1.f / (float)nth;
    float m   = red[32] * inv_n;
    float var = red[33] * inv_n - m * m;
    return make_float2(m, rsqrtf(var + 1e-5f));
}

// ---------------- K1: patch embed conv (stride 4) + LN(pe) ----------------
__global__ void k_patch(const float* __restrict__ x, const float* __restrict__ pw,
                        const float* __restrict__ pb, const float* __restrict__ peg,
                        const float* __restrict__ peb) {
    __shared__ float patch[48];
    __shared__ float red[34];
    int t   = blockIdx.x;            // b*1024 + hp*32 + wp
    int b   = t >> 10, l = t & 1023;
    int hp  = l >> 5,  wp = l & 31;
    int tid = threadIdx.x;           // channel c (192)
    if (tid < 48) {
        int ci = tid >> 4, ph = (tid >> 2) & 3, pwi = tid & 3;
        patch[tid] = x[((size_t)(b * CIN + ci) * IMG + hp * 4 + ph) * IMG + wp * 4 + pwi];
    }
    __syncthreads();
    float acc = pb[tid];
    const float* wr = pw + (size_t)tid * 48;
    #pragma unroll
    for (int j = 0; j < 48; j++) acc = fmaf(patch[j], wr[j], acc);
    float2 mv = block_meanvar(acc, tid, DIMC, red);
    g_y[(size_t)t * DIMC + tid] = (acc - mv.x) * mv.y * peg[tid] + peb[tid];
}

// ---------------- K2a: per-token LN (DIM) ----------------
__global__ void k_ln192(const float* __restrict__ g, const float* __restrict__ bgb) {
    __shared__ float red[34];
    int t = blockIdx.x, tid = threadIdx.x;
    float v = g_y[(size_t)t * DIMC + tid];
    float2 mv = block_meanvar(v, tid, DIMC, red);
    g_lny[(size_t)t * DIMC + tid] = (v - mv.x) * mv.y * g[tid] + bgb[tid];
}

// ---------------- tiled fp32 GEMM:  C[M,N] (+)= A[M,K] * B[N,K]^T ----------------
template <int BM, int BN, int BK, int TM, int TN, bool ACC>
__device__ __forceinline__ void sgemm_body(const float* __restrict__ A,
                                           const float* __restrict__ Bm,
                                           float* __restrict__ C,
                                           int M, int N, int Kd) {
    __shared__ float As[BK][BM + 4];
    __shared__ float Bs[BK][BN + 4];
    const int tid = threadIdx.x;                 // 256 threads
    const int tc  = tid % (BN / TN);             // 16
    const int tr  = tid / (BN / TN);             // 16
    const int bm  = blockIdx.y * BM;
    const int bn  = blockIdx.x * BN;
    float acc[TM][TN];
    #pragma unroll
    for (int i = 0; i < TM; i++)
        #pragma unroll
        for (int j = 0; j < TN; j++) acc[i][j] = 0.f;

    for (int k0 = 0; k0 < Kd; k0 += BK) {
        #pragma unroll
        for (int idx = tid; idx < BM * BK; idx += 256) {
            int i = idx / BK, kk = idx % BK;
            int m = bm + i, kg = k0 + kk;
            As[kk][i] = (m < M && kg < Kd) ? A[(size_t)m * Kd + kg] : 0.f;
        }
        #pragma unroll
        for (int idx = tid; idx < BN * BK; idx += 256) {
            int i = idx / BK, kk = idx % BK;
            int n = bn + i, kg = k0 + kk;
            Bs[kk][i] = (n < N && kg < Kd) ? Bm[(size_t)n * Kd + kg] : 0.f;
        }
        __syncthreads();
        #pragma unroll
        for (int kk = 0; kk < BK; kk++) {
            float4 a0 = *(const float4*)&As[kk][tr * TM];
            float4 a1 = *(const float4*)&As[kk][tr * TM + 4];
            float4 bv = *(const float4*)&Bs[kk][tc * TN];
            float av[8] = {a0.x, a0.y, a0.z, a0.w, a1.x, a1.y, a1.z, a1.w};
            float bw[4] = {bv.x, bv.y, bv.z, bv.w};
            #pragma unroll
            for (int i = 0; i < TM; i++)
                #pragma unroll
                for (int j = 0; j < TN; j++)
                    acc[i][j] = fmaf(av[i], bw[j], acc[i][j]);
        }
        __syncthreads();
    }
    #pragma unroll
    for (int i = 0; i < TM; i++) {
        int m = bm + tr * TM + i;
        if (m < M) {
            #pragma unroll
            for (int j = 0; j < TN; j++) {
                int n = bn + tc * TN + j;
                if (n < N) {
                    size_t o = (size_t)m * N + n;
                    C[o] = (ACC ? C[o] : 0.f) + acc[i][j];
                }
            }
        }
    }
}

__global__ __launch_bounds__(256) void k_gemm_in(const float* __restrict__ W) {
    sgemm_body<128, 64, 16, 8, 4, false>(g_lny, W, g_xz, NTOK, 2 * DIN, DIMC);
}
__global__ __launch_bounds__(256) void k_gemm_out(const float* __restrict__ W) {
    sgemm_body<128, 64, 16, 8, 4, true>(g_yo, W, g_y, NTOK, DIMC, DIN);
}

// ---------------- K3: depthwise 3x3 SAME conv + bias + silu ----------------
__global__ void k_dwconv(const float* __restrict__ cw, const float* __restrict__ cb) {
    int t = blockIdx.x;
    int b = t >> 10, l = t & 1023;
    int h = l >> 5,  w = l & 31;
    int d = threadIdx.x;
    const float* wr = cw + (size_t)d * 9;
    float acc = cb[d];
    #pragma unroll
    for (int kh = 0; kh < 3; kh++) {
        int hh = h + kh - 1;
        if (hh < 0 || hh >= HP) continue;
        #pragma unroll
        for (int kw = 0; kw < 3; kw++) {
            int ww = w + kw - 1;
            if (ww < 0 || ww >= HP) continue;
            acc = fmaf(g_xz[((size_t)(b * LTOK + hh * HP + ww)) * (2 * DIN) + d],
                       wr[kh * 3 + kw], acc);
        }
    }
    g_xc[(size_t)t * DIN + d] = silu_f(acc);
}

// direction-dependent spatial index for xs[b,k,:,l]
__device__ __forceinline__ int perm_l(int k, int l) {
    if (k == 0) return l;
    if (k == 1) return ((l & 31) << 5) | (l >> 5);
    if (k == 2) return 1023 - l;
    int m = 1023 - l;
    return ((m & 31) << 5) | (m >> 5);
}

// ---------------- K4: x_proj (44 outs) + dt GEMV + softplus, per (b,k,l) ----------------
__global__ __launch_bounds__(DIN) void k_xdbl(const float* __restrict__ xpw,
                                              const float* __restrict__ dtw,
                                              const float* __restrict__ dtb) {
    __shared__ float sx[DIN];
    __shared__ float proj[RR];
    int blk = blockIdx.x;                 // b*4096 + k*1024 + l
    int l = blk & 1023, k = (blk >> 10) & 3, b = blk >> 12;
    int tid = threadIdx.x;
    int sl = perm_l(k, l);
    sx[tid] = g_xc[((size_t)(b * LTOK) + sl) * DIN + tid];
    __syncthreads();
    if (tid < 352) {                      // 44 outputs x 8 lanes (11 full warps)
        int c = tid >> 3, ln = tid & 7;
        const float* wr = xpw + ((size_t)(k * 44 + c)) * DIN;
        float s = 0.f;
        #pragma unroll 8
        for (int dd = ln; dd < DIN; dd += 8) s = fmaf(sx[dd], wr[dd], s);
        #pragma unroll
        for (int o = 4; o; o >>= 1) s += __shfl_xor_sync(0xffffffffu, s, o);
        if (ln == 0) {
            if (c < RR) proj[c] = s;
            else        g_BC[(size_t)blk * 32 + (c - RR)] = s;  // Bs then Cs
        }
    }
    __syncthreads();
    float acc = dtb[k * DIN + tid];
    const float* dwr = dtw + ((size_t)(k * DIN + tid)) * RR;
    #pragma unroll
    for (int r = 0; r < RR; r++) acc = fmaf(proj[r], dwr[r], acc);
    // softplus(x) = max(x,0) + log1p(exp(-|x|))
    float sp = fmaxf(acc, 0.f) + __logf(1.f + fast_exp(-fabsf(acc)));
    g_dt[(size_t)blk * DIN + tid] = sp;
}

// ---------------- K5: selective scan, 2 threads per (b,k,d) chain ----------------
__global__ __launch_bounds__(128) void k_scan(const float* __restrict__ alog,
                                              const float* __restrict__ dsv) {
    __shared__ float sBC[64][32];
    int blk = blockIdx.x;                 // (b*4+k)*6 + dchunk
    int dchunk = blk % 6;
    int bk = blk / 6;
    int k = bk & 3, b = bk >> 2;
    int tid  = threadIdx.x;
    int p    = tid >> 1;                  // chain within chunk, 0..63
    int half = tid & 1;                   // which 8 states
    int d    = dchunk * 64 + p;

    float Areg[8];
    const float* ap = alog + ((size_t)(k * DIN + d)) * NS + half * 8;
    #pragma unroll
    for (int j = 0; j < 8; j++) Areg[j] = -__expf(ap[j]);
    float Dv = dsv[k * DIN + d];
    float h[8];
    #pragma unroll
    for (int j = 0; j < 8; j++) h[j] = 0.f;

    const float* dtp = g_dt + ((size_t)(b * 4 + k)) * LTOK * DIN + d;
    const float* bcp = g_BC + ((size_t)(b * 4 + k)) * LTOK * 32;
    const float* xcb = g_xc + (size_t)b * LTOK * DIN + d;
    float*       ysp = g_ys + ((size_t)(b * 4 + k)) * LTOK * DIN + d;

    for (int l0 = 0; l0 < LTOK; l0 += 64) {
        __syncthreads();
        const float4* src = (const float4*)(bcp + (size_t)l0 * 32);
        float4*       dst = (float4*)&sBC[0][0];
        #pragma unroll
        for (int i = 0; i < 4; i++) dst[i * 128 + tid] = src[i * 128 + tid];
        __syncthreads();
        for (int lc = 0; lc < 64; lc++) {
            int l = l0 + lc;
            float dtv = dtp[(size_t)l * DIN];
            int sl;
            if      (k == 0) sl = l;
            else if (k == 1) sl = ((l & 31) << 5) | (l >> 5);
            else if (k == 2) sl = 1023 - l;
            else { int m = 1023 - l; sl = ((m & 31) << 5) | (m >> 5); }
            float u  = xcb[(size_t)sl * DIN];
            float du = dtv * u;
            const float* bc = &sBC[lc][half * 8];
            float4 B0 = *(const float4*)bc;
            float4 B1 = *(const float4*)(bc + 4);
            float4 C0 = *(const float4*)(bc + 16);
            float4 C1 = *(const float4*)(bc + 20);
            float Bv[8] = {B0.x, B0.y, B0.z, B0.w, B1.x, B1.y, B1.z, B1.w};
            float Cv[8] = {C0.x, C0.y, C0.z, C0.w, C1.x, C1.y, C1.z, C1.w};
            float y = 0.f;
            #pragma unroll
            for (int j = 0; j < 8; j++) {
                float a = fast_exp(dtv * Areg[j]);
                h[j] = fmaf(a, h[j], du * Bv[j]);
                y    = fmaf(h[j], Cv[j], y);
            }
            y += __shfl_xor_sync(0xffffffffu, y, 1);
            if (!half) ysp[(size_t)l * DIN] = fmaf(Dv, u, y);
        }
    }
}

// ---------------- K6: combine 4 directions + out-LN + silu(z) gate ----------------
__global__ __launch_bounds__(DIN) void k_combine(const float* __restrict__ ong,
                                                 const float* __restrict__ onb) {
    __shared__ float red[34];
    int t = blockIdx.x;
    int b = t >> 10, l = t & 1023;
    int h = l >> 5,  w = l & 31;
    int d = threadIdx.x;
    int lT = (w << 5) | h;
    size_t base = (size_t)b * KDIR * LTOK * DIN;
    float v = g_ys[base + ((size_t)(0 * LTOK + l))          * DIN + d]
            + g_ys[base + ((size_t)(2 * LTOK + (1023 - l))) * DIN + d]
            + g_ys[base + ((size_t)(1 * LTOK + lT))         * DIN + d]
            + g_ys[base + ((size_t)(3 * LTOK + (1023 - lT)))* DIN + d];
    float2 mv = block_meanvar(v, d, DIN, red);
    float lnv = (v - mv.x) * mv.y * ong[d] + onb[d];
    float z   = g_xz[(size_t)t * (2 * DIN) + DIN + d];
    g_yo[(size_t)t * DIN + d] = lnv * silu_f(z);
}

// ---------------- K8: final LN -> output ----------------
__global__ void k_final(const float* __restrict__ g, const float* __restrict__ bgb,
                        float* __restrict__ out) {
    __shared__ float red[34];
    int t = blockIdx.x, tid = threadIdx.x;
    float v = g_y[(size_t)t * DIMC + tid];
    float2 mv = block_meanvar(v, tid, DIMC, red);
    out[(size_t)t * DIMC + tid] = (v - mv.x) * mv.y * g[tid] + bgb[tid];
}

// ---------------- launch ----------------
extern "C" void kernel_launch(void* const* d_in, const int* in_sizes, int n_in,
                              void* d_out, int out_size) {
    (void)in_sizes; (void)n_in; (void)out_size;
    const float* x          = (const float*)d_in[0];
    const float* patch_w    = (const float*)d_in[1];
    const float* patch_b    = (const float*)d_in[2];
    const float* pe_g       = (const float*)d_in[3];
    const float* pe_b       = (const float*)d_in[4];
    const float* ln_g       = (const float*)d_in[5];
    const float* ln_b       = (const float*)d_in[6];
    const float* in_proj_w  = (const float*)d_in[7];
    const float* conv_w     = (const float*)d_in[8];
    const float* conv_b     = (const float*)d_in[9];
    const float* x_proj_w   = (const float*)d_in[10];
    const float* dt_w       = (const float*)d_in[11];
    const float* dt_b       = (const float*)d_in[12];
    const float* A_log      = (const float*)d_in[13];
    const float* Ds         = (const float*)d_in[14];
    const float* out_norm_g = (const float*)d_in[15];
    const float* out_norm_b = (const float*)d_in[16];
    const float* out_proj_w = (const float*)d_in[17];
    const float* fin_g      = (const float*)d_in[18];
    const float* fin_b      = (const float*)d_in[19];

    k_patch<<<NTOK, DIMC>>>(x, patch_w, patch_b, pe_g, pe_b);

    for (int dep = 0; dep < DEPTH; dep++) {
        k_ln192<<<NTOK, DIMC>>>(ln_g + dep * DIMC, ln_b + dep * DIMC);
        k_gemm_in<<<dim3((2 * DIN) / 64, NTOK / 128), 256>>>(
            in_proj_w + (size_t)dep * 2 * DIN * DIMC);
        k_dwconv<<<NTOK, DIN>>>(conv_w + (size_t)dep * DIN * 9, conv_b + dep * DIN);
        k_xdbl<<<BB * KDIR * LTOK, DIN>>>(
            x_proj_w + (size_t)dep * KDIR * 44 * DIN,
            dt_w     + (size_t)dep * KDIR * DIN * RR,
            dt_b     + (size_t)dep * KDIR * DIN);
        k_scan<<<BB * KDIR * 6, 128>>>(
            A_log + (size_t)dep * KDIR * DIN * NS,
            Ds    + (size_t)dep * KDIR * DIN);
        k_combine<<<NTOK, DIN>>>(out_norm_g + dep * DIN, out_norm_b + dep * DIN);
        k_gemm_out<<<dim3(DIMC / 64, NTOK / 128), 256>>>(
            out_proj_w + (size_t)dep * DIMC * DIN);
    }

    k_final<<<NTOK, DIMC>>>(fin_g, fin_b, (float*)d_out);
}

// round 8
// speedup vs baseline: 2.0738x; 2.0738x over previous
#include <cuda_runtime.h>
#include <cstdint>
#include <cstddef>

// ---------------- problem constants ----------------
#define BB    8
#define CIN   3
#define IMG   128
#define PATCH 4
#define DIMC  192          // DIM
#define DEPTH 2
#define DIN   384          // 2*DIM
#define NS    16           // N (state)
#define RR    12           // R
#define KDIR  4            // K directions
#define HP    32
#define LTOK  1024         // L = HP*HP
#define NTOK  (BB*LTOK)    // 8192 tokens
#define NPROJ 176          // K*(R+2N) = 4*44

// ---------------- scratch (no cudaMalloc allowed) ----------------
__device__ alignas(16) float g_y  [(size_t)NTOK*DIMC];        // residual stream [t][c]
__device__ alignas(16) float g_lny[(size_t)NTOK*DIMC];        // LN'd stream     [t][c]
__device__ alignas(16) float g_xz [(size_t)NTOK*2*DIN];       // in_proj out     [t][768]
__device__ alignas(16) float g_xc [(size_t)NTOK*DIN];         // conv+silu out   [t][d]
__device__ alignas(16) float g_pj [(size_t)NTOK*NPROJ];       // x_proj out      [t][k*44+c]
__device__ alignas(16) float g_ys [(size_t)BB*KDIR*LTOK*DIN]; // scan out        [b][k][t][d] (token-indexed)
__device__ alignas(16) float g_yo [(size_t)NTOK*DIN];         // gated LN out    [t][d]

__device__ __forceinline__ float silu_f(float v) {
    return v / (1.f + __expf(-v));
}

// ---------------- block LayerNorm reduce (nth multiple of 32, <=512) ----------------
__device__ __forceinline__ float2 block_meanvar(float v, int tid, int nth, float* red) {
    float s = v, q = v * v;
    #pragma unroll
    for (int o = 16; o; o >>= 1) {
        s += __shfl_xor_sync(0xffffffffu, s, o);
        q += __shfl_xor_sync(0xffffffffu, q, o);
    }
    if ((tid & 31) == 0) { red[tid >> 5] = s; red[16 + (tid >> 5)] = q; }
    __syncthreads();
    if (tid < 32) {
        int nw = nth >> 5;
        float a = (tid < nw) ? red[tid]      : 0.f;
        float c = (tid < nw) ? red[16 + tid] : 0.f;
        #pragma unroll
        for (int o = 8; o; o >>= 1) {
            a += __shfl_xor_sync(0xffffffffu, a, o);
            c += __shfl_xor_sync(0xffffffffu, c, o);
        }
        if (tid == 0) { red[32] = a; red[33] = c; }
    }
    __syncthreads();
    float inv_n = 1.f / (float)nth;
    float m   = red[32] * inv_n;
    float var = red[33] * inv_n - m * m;
    return make_float2(m, rsqrtf(var + 1e-5f));
}

// direction-dependent spatial index: both the input gather AND output scatter
// position for scan step l in direction k.
__device__ __forceinline__ int perm_l(int k, int l) {
    if (k == 0) return l;
    if (k == 1) return ((l & 31) << 5) | (l >> 5);
    if (k == 2) return 1023 - l;
    int m = 1023 - l;
    return ((m & 31) << 5) | (m >> 5);
}

// ---------------- K1: patch embed conv (stride 4) + LN(pe) ----------------
__global__ void k_patch(const float* __restrict__ x, const float* __restrict__ pw,
                        const float* __restrict__ pb, const float* __restrict__ peg,
                        const float* __restrict__ peb) {
    __shared__ float patch[48];
    __shared__ float red[34];
    int t   = blockIdx.x;
    int b   = t >> 10, l = t & 1023;
    int hp  = l >> 5,  wp = l & 31;
    int tid = threadIdx.x;           // channel c (192)
    if (tid < 48) {
        int ci = tid >> 4, ph = (tid >> 2) & 3, pwi = tid & 3;
        patch[tid] = x[((size_t)(b * CIN + ci) * IMG + hp * 4 + ph) * IMG + wp * 4 + pwi];
    }
    __syncthreads();
    float acc = pb[tid];
    const float* wr = pw + (size_t)tid * 48;
    #pragma unroll
    for (int j = 0; j < 48; j++) acc = fmaf(patch[j], wr[j], acc);
    float2 mv = block_meanvar(acc, tid, DIMC, red);
    g_y[(size_t)t * DIMC + tid] = (acc - mv.x) * mv.y * peg[tid] + peb[tid];
}

// ---------------- K2: per-token LN (DIM) ----------------
__global__ void k_ln192(const float* __restrict__ g, const float* __restrict__ bgb) {
    __shared__ float red[34];
    int t = blockIdx.x, tid = threadIdx.x;
    float v = g_y[(size_t)t * DIMC + tid];
    float2 mv = block_meanvar(v, tid, DIMC, red);
    g_lny[(size_t)t * DIMC + tid] = (v - mv.x) * mv.y * g[tid] + bgb[tid];
}

// ---------------- tiled fp32 GEMM:  C[M,N] (+)= A[M,K] * B[N,K]^T ----------------
// 128 threads, BM=128, BN=64, BK=16, 8x8 per-thread microtile, register
// double-buffer on the global->smem path. Per kk: 4 LDS.128 feed 64 FMAs.
// M multiple of BM; Kd multiple of BK; N tail guarded.
#define GBM 128
#define GBN 64
#define GBK 16

template <bool ACC>
__device__ __forceinline__ void sgemm_body(const float* __restrict__ A,
                                           const float* __restrict__ Bm,
                                           float* __restrict__ C,
                                           int M, int N, int Kd) {
    __shared__ float As[GBK][GBM + 4];
    __shared__ float Bs[GBK][GBN + 4];
    const int tid = threadIdx.x;                 // 128 threads
    const int tc  = tid & 7;                     // 8 col groups
    const int tr  = tid >> 3;                    // 16 row groups
    const int bm  = blockIdx.y * GBM;
    const int bn  = blockIdx.x * GBN;

    // fixed per-thread staging indices:
    //   A: idx = tid + j*128, j=0..3  (512 = GBM*GBK/4 slots)
    //   B: idx = tid + j*128, j=0..1  (256 = GBN*GBK/4 slots)
    float4 pa[4], pb[2];

    #pragma unroll
    for (int j = 0; j < 4; j++) {
        int idx = tid + j * 128, i = idx >> 2, kq = idx & 3;
        pa[j] = *(const float4*)&A[(size_t)(bm + i) * Kd + kq * 4];
    }
    #pragma unroll
    for (int j = 0; j < 2; j++) {
        int idx = tid + j * 128, i = idx >> 2, kq = idx & 3;
        int n = bn + i;
        pb[j] = (n < N) ? *(const float4*)&Bm[(size_t)n * Kd + kq * 4]
                        : make_float4(0.f, 0.f, 0.f, 0.f);
    }

    float acc[8][8];
    #pragma unroll
    for (int i = 0; i < 8; i++)
        #pragma unroll
        for (int j = 0; j < 8; j++) acc[i][j] = 0.f;

    for (int k0 = 0; k0 < Kd; k0 += GBK) {
        // commit staged tile to smem
        #pragma unroll
        for (int j = 0; j < 4; j++) {
            int idx = tid + j * 128, i = idx >> 2, kq = idx & 3;
            As[kq * 4 + 0][i] = pa[j].x; As[kq * 4 + 1][i] = pa[j].y;
            As[kq * 4 + 2][i] = pa[j].z; As[kq * 4 + 3][i] = pa[j].w;
        }
        #pragma unroll
        for (int j = 0; j < 2; j++) {
            int idx = tid + j * 128, i = idx >> 2, kq = idx & 3;
            Bs[kq * 4 + 0][i] = pb[j].x; Bs[kq * 4 + 1][i] = pb[j].y;
            Bs[kq * 4 + 2][i] = pb[j].z; Bs[kq * 4 + 3][i] = pb[j].w;
        }
        __syncthreads();

        // prefetch next tile while computing this one
        int kn = k0 + GBK;
        if (kn < Kd) {
            #pragma unroll
            for (int j = 0; j < 4; j++) {
                int idx = tid + j * 128, i = idx >> 2, kq = idx & 3;
                pa[j] = *(const float4*)&A[(size_t)(bm + i) * Kd + kn + kq * 4];
            }
            #pragma unroll
            for (int j = 0; j < 2; j++) {
                int idx = tid + j * 128, i = idx >> 2, kq = idx & 3;
                int n = bn + i;
                pb[j] = (n < N) ? *(const float4*)&Bm[(size_t)n * Kd + kn + kq * 4]
                                : make_float4(0.f, 0.f, 0.f, 0.f);
            }
        }

        #pragma unroll
        for (int kk = 0; kk < GBK; kk++) {
            float4 a0 = *(const float4*)&As[kk][tr * 8];
            float4 a1 = *(const float4*)&As[kk][tr * 8 + 4];
            float4 b0 = *(const float4*)&Bs[kk][tc * 8];
            float4 b1 = *(const float4*)&Bs[kk][tc * 8 + 4];
            float av[8] = {a0.x, a0.y, a0.z, a0.w, a1.x, a1.y, a1.z, a1.w};
            float bw[8] = {b0.x, b0.y, b0.z, b0.w, b1.x, b1.y, b1.z, b1.w};
            #pragma unroll
            for (int i = 0; i < 8; i++)
                #pragma unroll
                for (int j = 0; j < 8; j++)
                    acc[i][j] = fmaf(av[i], bw[j], acc[i][j]);
        }
        __syncthreads();
    }
    #pragma unroll
    for (int i = 0; i < 8; i++) {
        int m = bm + tr * 8 + i;
        #pragma unroll
        for (int j = 0; j < 8; j++) {
            int n = bn + tc * 8 + j;
            if (n < N) {
                size_t o = (size_t)m * N + n;
                C[o] = (ACC ? C[o] : 0.f) + acc[i][j];
            }
        }
    }
}

__global__ __launch_bounds__(128) void k_gemm_in(const float* __restrict__ W) {
    sgemm_body<false>(g_lny, W, g_xz, NTOK, 2 * DIN, DIMC);
}
__global__ __launch_bounds__(128) void k_gemm_proj(const float* __restrict__ W) {
    sgemm_body<false>(g_xc, W, g_pj, NTOK, NPROJ, DIN);
}
__global__ __launch_bounds__(128) void k_gemm_out(const float* __restrict__ W) {
    sgemm_body<true>(g_yo, W, g_y, NTOK, DIMC, DIN);
}

// ---------------- K3: depthwise 3x3 SAME conv + bias + silu ----------------
__global__ void k_dwconv(const float* __restrict__ cw, const float* __restrict__ cb) {
    int t = blockIdx.x;
    int b = t >> 10, l = t & 1023;
    int h = l >> 5,  w = l & 31;
    int d = threadIdx.x;
    const float* wr = cw + (size_t)d * 9;
    float acc = cb[d];
    #pragma unroll
    for (int kh = 0; kh < 3; kh++) {
        int hh = h + kh - 1;
        if (hh < 0 || hh >= HP) continue;
        #pragma unroll
        for (int kw = 0; kw < 3; kw++) {
            int ww = w + kw - 1;
            if (ww < 0 || ww >= HP) continue;
            acc = fmaf(g_xz[((size_t)(b * LTOK + hh * HP + ww)) * (2 * DIN) + d],
                       wr[kh * 3 + kw], acc);
        }
    }
    g_xc[(size_t)t * DIN + d] = silu_f(acc);
}

// ---------------- K5: fused dt + selective scan ----------------
// Grid: 8*4*4 = 128 blocks, 384 threads.
// Block handles one (b, k) and a 96-wide d-chunk. 4 threads per chain (4 states each).
// Per 32-step chunk: stage proj rows (dt-inputs + B + C) and u into smem,
// compute the dt tile (12-FMA GEMV + softplus) into smem, then run 32 steps.
#define SC_CP 96   // chains per block
#define SC_CH 32   // steps per chunk

__global__ __launch_bounds__(384) void k_scan(const float* __restrict__ dtw,
                                              const float* __restrict__ dtb,
                                              const float* __restrict__ alog,
                                              const float* __restrict__ dsv) {
    __shared__ float s_pj [SC_CH][48];        // [0:12) dt-proj, [16:32) B, [32:48) C
    __shared__ float s_u  [SC_CH][SC_CP];
    __shared__ float s_dt [SC_CH][SC_CP];
    __shared__ float s_dtw[SC_CP * 13];       // [c][13] padded
    __shared__ float s_dtb[SC_CP];

    int blk    = blockIdx.x;
    int dchunk = blk & 3;
    int k      = (blk >> 2) & 3;
    int b      = blk >> 4;
    int tid    = threadIdx.x;
    int q      = tid & 3;                     // state quarter
    int p      = tid >> 2;                    // chain index 0..95
    int d0     = dchunk * SC_CP;
    int d      = d0 + p;

    // per-chain constants
    float A[4];
    const float* ap = alog + ((size_t)(k * DIN + d)) * NS + q * 4;
    #pragma unroll
    for (int j = 0; j < 4; j++) A[j] = -__expf(ap[j]);
    float Dv = dsv[k * DIN + d];

    // dt weights for this chunk's chains
    for (int idx = tid; idx < SC_CP * RR; idx += 384)
        s_dtw[(idx / RR) * 13 + idx % RR] = dtw[(size_t)(k * DIN + d0) * RR + idx];
    for (int idx = tid; idx < SC_CP; idx += 384)
        s_dtb[idx] = dtb[k * DIN + d0 + idx];

    float h[4];
    #pragma unroll
    for (int j = 0; j < 4; j++) h[j] = 0.f;

    const float* pjb = g_pj + (size_t)b * LTOK * NPROJ + k * 44;
    const float* xcb = g_xc + (size_t)b * LTOK * DIN + d0;
    float*       ysb = g_ys + ((size_t)(b * 4 + k)) * LTOK * DIN + d0;

    for (int l0 = 0; l0 < LTOK; l0 += SC_CH) {
        __syncthreads();
        // stage proj rows (44 floats each, B/C shifted +4 for alignment)
        for (int idx = tid; idx < SC_CH * 44; idx += 384) {
            int row = idx / 44, c = idx % 44;
            int sl  = perm_l(k, l0 + row);
            s_pj[row][c < RR ? c : c + 4] = pjb[(size_t)sl * NPROJ + c];
        }
        // stage u
        for (int idx = tid; idx < SC_CH * SC_CP; idx += 384) {
            int row = idx / SC_CP, pp = idx % SC_CP;
            int sl  = perm_l(k, l0 + row);
            s_u[row][pp] = xcb[(size_t)sl * DIN + pp];
        }
        __syncthreads();
        // compute dt tile: softplus(proj12 . dtw_c + dtb_c)
        for (int idx = tid; idx < SC_CH * SC_CP; idx += 384) {
            int c = idx % SC_CP, lc = idx / SC_CP;
            float acc = s_dtb[c];
            const float* wr = &s_dtw[c * 13];
            #pragma unroll
            for (int r = 0; r < RR; r++) acc = fmaf(s_pj[lc][r], wr[r], acc);
            s_dt[lc][c] = fmaxf(acc, 0.f) + __logf(1.f + __expf(-fabsf(acc)));
        }
        __syncthreads();
        // sequential scan over the chunk
        #pragma unroll 4
        for (int lc = 0; lc < SC_CH; lc++) {
            float dtv = s_dt[lc][p];
            float u   = s_u[lc][p];
            float du  = dtv * u;
            float4 Bv = *(const float4*)&s_pj[lc][16 + q * 4];
            float4 Cv = *(const float4*)&s_pj[lc][32 + q * 4];
            float y = 0.f;
            {
                float a0 = __expf(dtv * A[0]);
                float a1 = __expf(dtv * A[1]);
                float a2 = __expf(dtv * A[2]);
                float a3 = __expf(dtv * A[3]);
                h[0] = fmaf(a0, h[0], du * Bv.x);
                h[1] = fmaf(a1, h[1], du * Bv.y);
                h[2] = fmaf(a2, h[2], du * Bv.z);
                h[3] = fmaf(a3, h[3], du * Bv.w);
                y = fmaf(h[0], Cv.x, y);
                y = fmaf(h[1], Cv.y, y);
                y = fmaf(h[2], Cv.z, y);
                y = fmaf(h[3], Cv.w, y);
            }
            y += __shfl_xor_sync(0xffffffffu, y, 1);
            y += __shfl_xor_sync(0xffffffffu, y, 2);
            if (q == 0) {
                int sl = perm_l(k, l0 + lc);
                ysb[(size_t)sl * DIN + p] = fmaf(Dv, u, y);
            }
        }
    }
}

// ---------------- K6: combine 4 directions + out-LN + silu(z) gate ----------------
__global__ __launch_bounds__(DIN) void k_combine(const float* __restrict__ ong,
                                                 const float* __restrict__ onb) {
    __shared__ float red[34];
    int t = blockIdx.x;
    int b = t >> 10, l = t & 1023;
    int d = threadIdx.x;
    size_t base = (size_t)b * KDIR * LTOK * DIN + (size_t)l * DIN + d;
    float v = g_ys[base]
            + g_ys[base + (size_t)1 * LTOK * DIN]
            + g_ys[base + (size_t)2 * LTOK * DIN]
            + g_ys[base + (size_t)3 * LTOK * DIN];
    float2 mv = block_meanvar(v, d, DIN, red);
    float lnv = (v - mv.x) * mv.y * ong[d] + onb[d];
    float z   = g_xz[(size_t)t * (2 * DIN) + DIN + d];
    g_yo[(size_t)t * DIN + d] = lnv * silu_f(z);
}

// ---------------- K8: final LN -> output ----------------
__global__ void k_final(const float* __restrict__ g, const float* __restrict__ bgb,
                        float* __restrict__ out) {
    __shared__ float red[34];
    int t = blockIdx.x, tid = threadIdx.x;
    float v = g_y[(size_t)t * DIMC + tid];
    float2 mv = block_meanvar(v, tid, DIMC, red);
    out[(size_t)t * DIMC + tid] = (v - mv.x) * mv.y * g[tid] + bgb[tid];
}

// ---------------- launch ----------------
extern "C" void kernel_launch(void* const* d_in, const int* in_sizes, int n_in,
                              void* d_out, int out_size) {
    (void)in_sizes; (void)n_in; (void)out_size;
    const float* x          = (const float*)d_in[0];
    const float* patch_w    = (const float*)d_in[1];
    const float* patch_b    = (const float*)d_in[2];
    const float* pe_g       = (const float*)d_in[3];
    const float* pe_b       = (const float*)d_in[4];
    const float* ln_g       = (const float*)d_in[5];
    const float* ln_b       = (const float*)d_in[6];
    const float* in_proj_w  = (const float*)d_in[7];
    const float* conv_w     = (const float*)d_in[8];
    const float* conv_b     = (const float*)d_in[9];
    const float* x_proj_w   = (const float*)d_in[10];
    const float* dt_w       = (const float*)d_in[11];
    const float* dt_b       = (const float*)d_in[12];
    const float* A_log      = (const float*)d_in[13];
    const float* Ds         = (const float*)d_in[14];
    const float* out_norm_g = (const float*)d_in[15];
    const float* out_norm_b = (const float*)d_in[16];
    const float* out_proj_w = (const float*)d_in[17];
    const float* fin_g      = (const float*)d_in[18];
    const float* fin_b      = (const float*)d_in[19];

    k_patch<<<NTOK, DIMC>>>(x, patch_w, patch_b, pe_g, pe_b);

    for (int dep = 0; dep < DEPTH; dep++) {
        k_ln192<<<NTOK, DIMC>>>(ln_g + dep * DIMC, ln_b + dep * DIMC);
        k_gemm_in<<<dim3((2 * DIN) / GBN, NTOK / GBM), 128>>>(
            in_proj_w + (size_t)dep * 2 * DIN * DIMC);
        k_dwconv<<<NTOK, DIN>>>(conv_w + (size_t)dep * DIN * 9, conv_b + dep * DIN);
        k_gemm_proj<<<dim3((NPROJ + GBN - 1) / GBN, NTOK / GBM), 128>>>(
            x_proj_w + (size_t)dep * NPROJ * DIN);
        k_scan<<<BB * KDIR * 4, 384>>>(
            dt_w  + (size_t)dep * KDIR * DIN * RR,
            dt_b  + (size_t)dep * KDIR * DIN,
            A_log + (size_t)dep * KDIR * DIN * NS,
            Ds    + (size_t)dep * KDIR * DIN);
        k_combine<<<NTOK, DIN>>>(out_norm_g + dep * DIN, out_norm_b + dep * DIN);
        k_gemm_out<<<dim3(DIMC / GBN, NTOK / GBM), 128>>>(
            out_proj_w + (size_t)dep * DIMC * DIN);
    }

    k_final<<<NTOK, DIMC>>>(fin_g, fin_b, (float*)d_out);
}